// round 2
// baseline (speedup 1.0000x reference)
#include <cuda_runtime.h>
#include <math.h>

// ---------------- problem constants ----------------
#define BB   8
#define CC   128
#define H0   62
#define W0   62
#define HH   64
#define WW   64
#define HP   66
#define WP   66
#define GG   4
#define PP   9
#define GC   32
#define NPIX (BB*HH*WW)        // 32768
#define NOM  108               // 72 offsets + 36 mask logits

// ---------------- scratch (device globals; no malloc allowed) ----------------
__device__ float g_xpad[BB*HH*WW*CC];   // x transposed to NHWC, zero-padded ring (GEMM1 A)
__device__ float g_y   [BB*HH*WW*CC];   // y = conv1x1 output, NHWC
__device__ float g_xp  [BB*HP*WP*CC];   // x_proj, spatially padded by 1, NHWC
__device__ float g_d   [BB*HH*WW*CC];   // dw+LN+GELU output, NHWC
__device__ float g_om  [NPIX*NOM];      // offsets(72) + mask logits(36)
__device__ float g_sam [NPIX*CC];       // sampled output, NHWC
__device__ float g_cwt [CC*CC];         // conv_w transposed to [K][N]
__device__ float g_wcat[CC*NOM];        // [off_w | mask_w] : [128][108]
__device__ float g_bcat[NOM];

// ---------------- weight prep ----------------
__global__ void prep_weights_kernel(const float* __restrict__ conv_w,
                                    const float* __restrict__ off_w,
                                    const float* __restrict__ mask_w,
                                    const float* __restrict__ off_b,
                                    const float* __restrict__ mask_b) {
    int idx = blockIdx.x * blockDim.x + threadIdx.x;
    const int T1 = CC*CC;            // 16384
    const int T2 = T1 + CC*NOM;      // 30208
    const int T3 = T2 + NOM;         // 30316
    if (idx < T1) {
        int k = idx / CC, c = idx % CC;
        g_cwt[k*CC + c] = conv_w[c*CC + k];
    } else if (idx < T2) {
        int t = idx - T1;
        int k = t / NOM, n = t % NOM;
        g_wcat[t] = (n < 72) ? off_w[k*72 + n] : mask_w[k*36 + (n - 72)];
    } else if (idx < T3) {
        int n = idx - T2;
        g_bcat[n] = (n < 72) ? off_b[n] : mask_b[n - 72];
    }
}

// ---------------- zero fill (float4) ----------------
__global__ void zero_kernel(float4* __restrict__ p, int n4) {
    int i = blockIdx.x * blockDim.x + threadIdx.x;
    if (i < n4) p[i] = make_float4(0.f, 0.f, 0.f, 0.f);
}

// ---------------- NCHW -> NHWC transpose with pad ring of zeros ----------------
// grid: (BB*HH, WW/32, CC/32), block (32,32)
__global__ void transpose_pad_kernel(const float* __restrict__ x) {
    __shared__ float s[32][33];
    int bi = blockIdx.x;           // b*64 + i
    int b  = bi >> 6;
    int i  = bi & 63;
    int j0 = blockIdx.y * 32;
    int c0 = blockIdx.z * 32;
    int tx = threadIdx.x, ty = threadIdx.y;
    int j = j0 + tx;               // read: tx = w
    float v = 0.f;
    if (i >= 1 && i <= 62 && j >= 1 && j <= 62) {
        v = x[((b*CC + c0 + ty)*H0 + (i - 1))*W0 + (j - 1)];
    }
    s[ty][tx] = v;
    __syncthreads();
    // write: tx = c, ty = w
    int jw = j0 + ty;
    g_xpad[((b*HH + i)*WW + jw)*CC + c0 + tx] = s[tx][ty];
}

// ---------------- generic GEMM: C[M,N] = A[M,128] * B[128,N] + bias ----------------
// BM=128, BN=128, BK=8, 256 threads, 8x8 micro-tile per thread.
// mode 0: row-major C (ldc=N); mode 1: store into g_xp at (i+1,j+1); mode 2: NCHW scatter
__global__ __launch_bounds__(256) void gemm128_kernel(
    const float* __restrict__ A, const float* __restrict__ Bm,
    const float* __restrict__ bias, float* __restrict__ C,
    int N, int mode) {
    __shared__ float As[8][132];
    __shared__ float Bs[8][128];
    int tid = threadIdx.x;
    int m0 = blockIdx.y * 128;
    int n0 = blockIdx.x * 128;
    int mb = (tid >> 4) * 8;
    int nb = (tid & 15) * 8;
    int arow = tid >> 1, acol = (tid & 1) * 4;
    int brow = tid >> 5, bcol = (tid & 31) * 4;

    float acc[8][8];
#pragma unroll
    for (int i = 0; i < 8; i++)
#pragma unroll
        for (int j = 0; j < 8; j++) acc[i][j] = 0.f;

    for (int k0 = 0; k0 < 128; k0 += 8) {
        float4 av = *reinterpret_cast<const float4*>(&A[(m0 + arow)*128 + k0 + acol]);
        As[acol + 0][arow] = av.x;
        As[acol + 1][arow] = av.y;
        As[acol + 2][arow] = av.z;
        As[acol + 3][arow] = av.w;
#pragma unroll
        for (int q = 0; q < 4; q++) {
            int n = n0 + bcol + q;
            Bs[brow][bcol + q] = (n < N) ? Bm[(k0 + brow)*N + n] : 0.f;
        }
        __syncthreads();
#pragma unroll
        for (int kk = 0; kk < 8; kk++) {
            float4 a0 = *reinterpret_cast<const float4*>(&As[kk][mb]);
            float4 a1 = *reinterpret_cast<const float4*>(&As[kk][mb + 4]);
            float4 b0 = *reinterpret_cast<const float4*>(&Bs[kk][nb]);
            float4 b1 = *reinterpret_cast<const float4*>(&Bs[kk][nb + 4]);
            float ar[8] = {a0.x, a0.y, a0.z, a0.w, a1.x, a1.y, a1.z, a1.w};
            float br[8] = {b0.x, b0.y, b0.z, b0.w, b1.x, b1.y, b1.z, b1.w};
#pragma unroll
            for (int i = 0; i < 8; i++)
#pragma unroll
                for (int j = 0; j < 8; j++) acc[i][j] += ar[i] * br[j];
        }
        __syncthreads();
    }

    float bv[8];
#pragma unroll
    for (int j = 0; j < 8; j++) {
        int n = n0 + nb + j;
        bv[j] = (n < N) ? bias[n] : 0.f;
    }
#pragma unroll
    for (int i = 0; i < 8; i++) {
        int m = m0 + mb + i;
        int b = m >> 12;
        int rem = m & 4095;
        if (mode == 0) {
#pragma unroll
            for (int j = 0; j < 8; j++) {
                int n = n0 + nb + j;
                if (n < N) C[m*N + n] = acc[i][j] + bv[j];
            }
        } else if (mode == 1) {
            int r = rem >> 6, cl = rem & 63;
            int base = ((b*HP + (r + 1))*WP + (cl + 1))*CC;
#pragma unroll
            for (int j = 0; j < 8; j++) C[base + n0 + nb + j] = acc[i][j] + bv[j];
        } else {
#pragma unroll
            for (int j = 0; j < 8; j++) {
                int n = n0 + nb + j;
                C[b*(CC*HH*WW) + n*(HH*WW) + rem] = acc[i][j] + bv[j];
            }
        }
    }
}

// ---------------- fused depthwise 3x3 + LayerNorm + GELU(exact) ----------------
// warp per pixel; lane handles 4 channels (lane*4 .. lane*4+3); block 256 = 8 pixels
__global__ __launch_bounds__(256) void dw_ln_gelu_kernel(
    const float* __restrict__ dw_w, const float* __restrict__ dw_b,
    const float* __restrict__ ln_g, const float* __restrict__ ln_b) {
    __shared__ float dws[CC*9];
    int tid = threadIdx.x;
    for (int t = tid; t < CC*9; t += 256) dws[t] = dw_w[t];
    __syncthreads();

    int warp = tid >> 5, lane = tid & 31;
    int pix = blockIdx.x * 8 + warp;
    int b = pix >> 12;
    int rem = pix & 4095;
    int i = rem >> 6, j = rem & 63;
    int c4 = lane * 4;

    float4 db = *reinterpret_cast<const float4*>(&dw_b[c4]);
    float v[4] = {db.x, db.y, db.z, db.w};
#pragma unroll
    for (int ky = 0; ky < 3; ky++) {
#pragma unroll
        for (int kx = 0; kx < 3; kx++) {
            int yy = i + ky - 1, xx = j + kx - 1;
            if ((unsigned)yy < (unsigned)HH && (unsigned)xx < (unsigned)WW) {
                float4 yv = *reinterpret_cast<const float4*>(
                    &g_y[((b*HH + yy)*WW + xx)*CC + c4]);
                int t = ky*3 + kx;
                v[0] += yv.x * dws[(c4 + 0)*9 + t];
                v[1] += yv.y * dws[(c4 + 1)*9 + t];
                v[2] += yv.z * dws[(c4 + 2)*9 + t];
                v[3] += yv.w * dws[(c4 + 3)*9 + t];
            }
        }
    }
    // LayerNorm over 128 channels (warp allreduce)
    float s = v[0] + v[1] + v[2] + v[3];
#pragma unroll
    for (int o = 16; o; o >>= 1) s += __shfl_xor_sync(0xffffffffu, s, o);
    float mu = s * (1.f / 128.f);
    float d2 = 0.f;
#pragma unroll
    for (int q = 0; q < 4; q++) { float t = v[q] - mu; d2 += t * t; }
#pragma unroll
    for (int o = 16; o; o >>= 1) d2 += __shfl_xor_sync(0xffffffffu, d2, o);
    float inv = rsqrtf(d2 * (1.f / 128.f) + 1e-5f);

    float4 lg = *reinterpret_cast<const float4*>(&ln_g[c4]);
    float4 lb = *reinterpret_cast<const float4*>(&ln_b[c4]);
    float gv[4] = {lg.x, lg.y, lg.z, lg.w};
    float bvv[4] = {lb.x, lb.y, lb.z, lb.w};
    float4 outv;
    float* op = reinterpret_cast<float*>(&outv);
#pragma unroll
    for (int q = 0; q < 4; q++) {
        float t = (v[q] - mu) * inv * gv[q] + bvv[q];
        op[q] = 0.5f * t * (1.f + erff(t * 0.70710678118654752440f));
    }
    *reinterpret_cast<float4*>(&g_d[pix*CC + c4]) = outv;
}

// ---------------- DCNv3 core: softmax(mask) + bilinear sampling ----------------
// block 128 = one pixel, warp g handles group g (lane = channel within group)
__global__ __launch_bounds__(128) void sample_kernel() {
    int pix = blockIdx.x;
    int g = threadIdx.x >> 5, lane = threadIdx.x & 31;
    int b = pix >> 12;
    int rem = pix & 4095;
    int i = rem >> 6, j = rem & 63;
    const float* omr = g_om + (size_t)pix * NOM;

    // softmax over the 9 mask logits of this group (redundant per-lane, broadcast loads)
    float lg[9];
    float mx = -1e30f;
#pragma unroll
    for (int p = 0; p < 9; p++) { lg[p] = omr[72 + g*9 + p]; mx = fmaxf(mx, lg[p]); }
    float sum = 0.f;
#pragma unroll
    for (int p = 0; p < 9; p++) { lg[p] = expf(lg[p] - mx); sum += lg[p]; }
    float minv = 1.f / sum;

    int cbase = g*GC + lane;
    const float* xpb = g_xp + (size_t)b * (HP*WP*CC);
    float acc = 0.f;
#pragma unroll
    for (int p = 0; p < 9; p++) {
        float offx = omr[(g*9 + p)*2 + 0];
        float offy = omr[(g*9 + p)*2 + 1];
        // ix = j + 1 + (p/3 - 1) + offx ; iy = i + 1 + (p%3 - 1) + offy
        float ix = (float)(j + p/3) + offx;
        float iy = (float)(i + (p - (p/3)*3)) + offy;
        float x0f = floorf(ix), y0f = floorf(iy);
        float wx1 = ix - x0f, wy1 = iy - y0f;
        float wx0 = 1.f - wx1, wy0 = 1.f - wy1;
        int x0 = (int)x0f, y0 = (int)y0f;
        float v00 = 0.f, v10 = 0.f, v01 = 0.f, v11 = 0.f;
        bool xv0 = (x0 >= 0) & (x0 < WP);
        bool xv1 = (x0 + 1 >= 0) & (x0 + 1 < WP);
        bool yv0 = (y0 >= 0) & (y0 < HP);
        bool yv1 = (y0 + 1 >= 0) & (y0 + 1 < HP);
        if (yv0) {
            if (xv0) v00 = xpb[(y0*WP + x0)*CC + cbase];
            if (xv1) v10 = xpb[(y0*WP + x0 + 1)*CC + cbase];
        }
        if (yv1) {
            if (xv0) v01 = xpb[((y0 + 1)*WP + x0)*CC + cbase];
            if (xv1) v11 = xpb[((y0 + 1)*WP + x0 + 1)*CC + cbase];
        }
        float bi = (v00*wx0 + v10*wx1)*wy0 + (v01*wx0 + v11*wx1)*wy1;
        acc += (lg[p] * minv) * bi;
    }
    g_sam[(size_t)pix*CC + cbase] = acc;
}

// ---------------- launch ----------------
extern "C" void kernel_launch(void* const* d_in, const int* in_sizes, int n_in,
                              void* d_out, int out_size) {
    const float* x          = (const float*)d_in[0];
    const float* conv_w     = (const float*)d_in[1];
    const float* conv_b     = (const float*)d_in[2];
    const float* in_proj_w  = (const float*)d_in[3];
    const float* in_proj_b  = (const float*)d_in[4];
    const float* dw_w       = (const float*)d_in[5];
    const float* dw_b       = (const float*)d_in[6];
    const float* ln_g       = (const float*)d_in[7];
    const float* ln_b       = (const float*)d_in[8];
    const float* off_w      = (const float*)d_in[9];
    const float* off_b      = (const float*)d_in[10];
    const float* mask_w     = (const float*)d_in[11];
    const float* mask_b     = (const float*)d_in[12];
    const float* out_proj_w = (const float*)d_in[13];
    const float* out_proj_b = (const float*)d_in[14];
    float* out = (float*)d_out;

    float *p_xpad, *p_y, *p_xp, *p_d, *p_om, *p_sam, *p_cwt, *p_wcat, *p_bcat;
    cudaGetSymbolAddress((void**)&p_xpad, g_xpad);
    cudaGetSymbolAddress((void**)&p_y,    g_y);
    cudaGetSymbolAddress((void**)&p_xp,   g_xp);
    cudaGetSymbolAddress((void**)&p_d,    g_d);
    cudaGetSymbolAddress((void**)&p_om,   g_om);
    cudaGetSymbolAddress((void**)&p_sam,  g_sam);
    cudaGetSymbolAddress((void**)&p_cwt,  g_cwt);
    cudaGetSymbolAddress((void**)&p_wcat, g_wcat);
    cudaGetSymbolAddress((void**)&p_bcat, g_bcat);

    // 1. zero the padded x_proj buffer (border ring must be 0 every replay)
    {
        int n4 = (BB*HP*WP*CC) / 4;
        zero_kernel<<<(n4 + 255)/256, 256>>>((float4*)p_xp, n4);
    }
    // 2. weight prep
    prep_weights_kernel<<<(30316 + 255)/256, 256>>>(conv_w, off_w, mask_w, off_b, mask_b);
    // 3. NCHW -> NHWC transpose + zero pad ring
    {
        dim3 grid(BB*HH, WW/32, CC/32);
        dim3 block(32, 32);
        transpose_pad_kernel<<<grid, block>>>(x);
    }
    // 4. GEMM1: y = xpad @ conv_w^T + conv_b   (NHWC)
    gemm128_kernel<<<dim3(1, NPIX/128), 256>>>(p_xpad, p_cwt, conv_b, p_y, 128, 0);
    // 5. GEMM2: x_proj = y @ in_proj_w + in_proj_b -> padded buffer g_xp
    gemm128_kernel<<<dim3(1, NPIX/128), 256>>>(p_y, in_proj_w, in_proj_b, p_xp, 128, 1);
    // 6. depthwise + LN + GELU -> g_d
    dw_ln_gelu_kernel<<<NPIX/8, 256>>>(dw_w, dw_b, ln_g, ln_b);
    // 7. GEMM3: [offset | mask_logits] = d @ wcat + bcat
    gemm128_kernel<<<dim3(1, NPIX/128), 256>>>(p_d, p_wcat, p_bcat, p_om, NOM, 0);
    // 8. softmax + bilinear sampling -> g_sam
    sample_kernel<<<NPIX, 128>>>();
    // 9. GEMM4: out = sampled @ out_proj_w + out_proj_b, scattered to NCHW
    gemm128_kernel<<<dim3(1, NPIX/128), 256>>>(p_sam, out_proj_w, out_proj_b, out, 128, 2);
}

// round 4
// speedup vs baseline: 1.5787x; 1.5787x over previous
#include <cuda_runtime.h>
#include <math.h>
#include <stdint.h>

// ---------------- problem constants ----------------
#define BB   8
#define CC   128
#define H0   62
#define W0   62
#define HH   64
#define WW   64
#define HP   66
#define WP   66
#define GG   4
#define PP   9
#define GC   32
#define NPIX (BB*HH*WW)        // 32768
#define OMS  128               // padded om row stride (72 off + 36 logits + 20 pad)

// ---------------- scratch (device globals) ----------------
__device__ float g_xpad[BB*HH*WW*CC];   // x in NHWC, zero ring (GEMM1 A)
__device__ float g_y   [BB*HH*WW*CC];   // conv1x1 output NHWC
__device__ float g_xp  [BB*HP*WP*CC];   // x_proj padded NHWC
__device__ float g_d   [BB*HH*WW*CC];   // dw+LN+GELU NHWC
__device__ float g_om  [NPIX*OMS];      // offsets(72)+logits(36)+pad
__device__ float g_sam [NPIX*CC];       // sampled NHWC
__device__ float g_bt  [4*128*128];     // 4 pre-transposed tf32 B tiles, [k][n]
__device__ float g_bcat[128];           // padded off/mask bias

// ---------------- helpers ----------------
__device__ __forceinline__ float f2tf(float x) {
    uint32_t u;
    asm("cvt.rn.tf32.f32 %0, %1;" : "=r"(u) : "f"(x));
    return __uint_as_float(u);
}
__device__ __forceinline__ void mma_tf32(float c[4], const uint32_t a[4],
                                         uint32_t b0, uint32_t b1) {
    asm volatile(
        "mma.sync.aligned.m16n8k8.row.col.f32.tf32.tf32.f32 "
        "{%0,%1,%2,%3}, {%4,%5,%6,%7}, {%8,%9}, {%0,%1,%2,%3};"
        : "+f"(c[0]), "+f"(c[1]), "+f"(c[2]), "+f"(c[3])
        : "r"(a[0]), "r"(a[1]), "r"(a[2]), "r"(a[3]), "r"(b0), "r"(b1));
}

// ---------------- weight prep: tf32 B tiles [k][n] + padded bias ----------------
__global__ void prep_weights_kernel(const float* __restrict__ conv_w,
                                    const float* __restrict__ in_proj_w,
                                    const float* __restrict__ off_w,
                                    const float* __restrict__ mask_w,
                                    const float* __restrict__ off_b,
                                    const float* __restrict__ mask_b,
                                    const float* __restrict__ out_proj_w) {
    int idx = blockIdx.x * blockDim.x + threadIdx.x;
    const int TB = 4 * 128 * 128;
    if (idx < TB) {
        int w = idx >> 14;
        int rem = idx & 16383;
        int k = rem >> 7, n = rem & 127;
        float v;
        if (w == 0)      v = conv_w[n * 128 + k];            // (Cout,Cin,1,1) -> B[k][n]=W[n][k]
        else if (w == 1) v = in_proj_w[k * 128 + n];
        else if (w == 2) v = (n < 72) ? off_w[k * 72 + n]
                           : (n < 108) ? mask_w[k * 36 + (n - 72)] : 0.f;
        else             v = out_proj_w[k * 128 + n];
        g_bt[idx] = f2tf(v);
    } else if (idx < TB + 128) {
        int n = idx - TB;
        g_bcat[n] = (n < 72) ? off_b[n] : (n < 108) ? mask_b[n - 72] : 0.f;
    }
}

// ---------------- zero only the pad ring of g_xp ----------------
__global__ void ring_zero_kernel() {
    int idx = blockIdx.x * blockDim.x + threadIdx.x;   // 8*260*32
    if (idx >= BB * 260 * 32) return;
    int c4 = (idx & 31) * 4;
    int t = idx >> 5;
    int b = t / 260, p = t % 260;
    int r, cl;
    if (p < 66)       { r = 0;        cl = p; }
    else if (p < 132) { r = 65;       cl = p - 66; }
    else if (p < 196) { r = p - 131;  cl = 0; }
    else              { r = p - 195;  cl = 65; }
    *reinterpret_cast<float4*>(&g_xp[(((size_t)b * HP + r) * WP + cl) * CC + c4]) =
        make_float4(0.f, 0.f, 0.f, 0.f);
}

// ---------------- NCHW -> NHWC transpose with zero pad ring ----------------
__global__ void transpose_pad_kernel(const float* __restrict__ x) {
    __shared__ float s[32][33];
    int bi = blockIdx.x;
    int b = bi >> 6, i = bi & 63;
    int j0 = blockIdx.y * 32, c0 = blockIdx.z * 32;
    int tx = threadIdx.x, ty = threadIdx.y;
    int j = j0 + tx;
    float v = 0.f;
    if (i >= 1 && i <= 62 && j >= 1 && j <= 62)
        v = x[((b * CC + c0 + ty) * H0 + (i - 1)) * W0 + (j - 1)];
    s[ty][tx] = v;
    __syncthreads();
    int jw = j0 + ty;
    g_xpad[((b * HH + i) * WW + jw) * CC + c0 + tx] = s[tx][ty];
}

// ---------------- tensor-core tf32 GEMM via mma.sync (sm_80+ path) ----------------
// C[32768,128] = A[32768,128] @ B[128,128] + bias.
// CTA: 128x128x128 tile, 256 threads = 8 warps (4 m x 2 n), warp tile 32x64.
// modes: 0 row-major ldc=128, 1 padded g_xp store, 2 NCHW scatter
#define LDA 132
__global__ __launch_bounds__(256) void mma_gemm_kernel(
    const float* __restrict__ A, const float* __restrict__ Bt,
    const float* __restrict__ bias, float* __restrict__ C, int mode) {
    extern __shared__ float sm[];
    float* sA = sm;              // [128][132]
    float* sB = sm + 128 * LDA; // [128][132] (k-major)
    int tid = threadIdx.x;
    int w = tid >> 5, lane = tid & 31;
    int g = lane >> 2, tig = lane & 3;
    int wm = w >> 1, wn = w & 1;
    int m0 = blockIdx.x * 128;

    // coalesced loads: 4096 float4 per tile, 16 per thread
#pragma unroll
    for (int it = 0; it < 16; it++) {
        int idx = it * 256 + tid;
        int r = idx >> 5, c4 = (idx & 31) * 4;
        float4 v = *reinterpret_cast<const float4*>(&A[(size_t)(m0 + r) * 128 + c4]);
        v.x = f2tf(v.x); v.y = f2tf(v.y); v.z = f2tf(v.z); v.w = f2tf(v.w);
        *reinterpret_cast<float4*>(&sA[r * LDA + c4]) = v;
        *reinterpret_cast<float4*>(&sB[r * LDA + c4]) =
            *reinterpret_cast<const float4*>(&Bt[(size_t)r * 128 + c4]);
    }
    __syncthreads();

    float acc[2][8][4];
#pragma unroll
    for (int mt = 0; mt < 2; mt++)
#pragma unroll
        for (int nt = 0; nt < 8; nt++)
#pragma unroll
            for (int q = 0; q < 4; q++) acc[mt][nt][q] = 0.f;

#pragma unroll
    for (int ks = 0; ks < 16; ks++) {
        int k0 = ks * 8;
        uint32_t af[2][4];
#pragma unroll
        for (int mt = 0; mt < 2; mt++) {
            int rb = wm * 32 + mt * 16 + g;
            af[mt][0] = __float_as_uint(sA[rb * LDA + k0 + tig]);
            af[mt][1] = __float_as_uint(sA[(rb + 8) * LDA + k0 + tig]);
            af[mt][2] = __float_as_uint(sA[rb * LDA + k0 + tig + 4]);
            af[mt][3] = __float_as_uint(sA[(rb + 8) * LDA + k0 + tig + 4]);
        }
#pragma unroll
        for (int nt = 0; nt < 8; nt++) {
            int cb = wn * 64 + nt * 8 + g;
            uint32_t b0 = __float_as_uint(sB[(k0 + tig) * LDA + cb]);
            uint32_t b1 = __float_as_uint(sB[(k0 + tig + 4) * LDA + cb]);
            mma_tf32(acc[0][nt], af[0], b0, b1);
            mma_tf32(acc[1][nt], af[1], b0, b1);
        }
    }

    // epilogue: c0,c1 -> (row g, cols 2tig,2tig+1); c2,c3 -> (row g+8)
#pragma unroll
    for (int mt = 0; mt < 2; mt++) {
        int ml = wm * 32 + mt * 16;
        int m_a = m0 + ml + g;        // rows for c0,c1
        int m_b = m_a + 8;            // rows for c2,c3
        int ba = m_a >> 12, ra = m_a & 4095;
        int bb = m_b >> 12, rb = m_b & 4095;
#pragma unroll
        for (int nt = 0; nt < 8; nt++) {
            int cb = wn * 64 + nt * 8 + 2 * tig;
            float bx = __ldg(&bias[cb]), by = __ldg(&bias[cb + 1]);
            float2 oa = make_float2(acc[mt][nt][0] + bx, acc[mt][nt][1] + by);
            float2 ob = make_float2(acc[mt][nt][2] + bx, acc[mt][nt][3] + by);
            if (mode == 0) {
                *reinterpret_cast<float2*>(&C[(size_t)m_a * 128 + cb]) = oa;
                *reinterpret_cast<float2*>(&C[(size_t)m_b * 128 + cb]) = ob;
            } else if (mode == 1) {
                int r1 = ra >> 6, c1 = ra & 63;
                int r2 = rb >> 6, c2 = rb & 63;
                *reinterpret_cast<float2*>(
                    &C[(((size_t)ba * HP + r1 + 1) * WP + c1 + 1) * CC + cb]) = oa;
                *reinterpret_cast<float2*>(
                    &C[(((size_t)bb * HP + r2 + 1) * WP + c2 + 1) * CC + cb]) = ob;
            } else {
                C[((size_t)ba * CC + cb    ) * 4096 + ra] = oa.x;
                C[((size_t)ba * CC + cb + 1) * 4096 + ra] = oa.y;
                C[((size_t)bb * CC + cb    ) * 4096 + rb] = ob.x;
                C[((size_t)bb * CC + cb + 1) * 4096 + rb] = ob.y;
            }
        }
    }
}

// ---------------- fused depthwise 3x3 + LayerNorm + GELU ----------------
__global__ __launch_bounds__(256) void dw_ln_gelu_kernel(
    const float* __restrict__ dw_w, const float* __restrict__ dw_b,
    const float* __restrict__ ln_g, const float* __restrict__ ln_b) {
    __shared__ float dws[CC * 9];
    int tid = threadIdx.x;
    for (int t = tid; t < CC * 9; t += 256) dws[t] = dw_w[t];
    __syncthreads();

    int warp = tid >> 5, lane = tid & 31;
    int pix = blockIdx.x * 8 + warp;
    int b = pix >> 12, rem = pix & 4095;
    int i = rem >> 6, j = rem & 63;
    int c4 = lane * 4;

    float4 db = *reinterpret_cast<const float4*>(&dw_b[c4]);
    float v[4] = {db.x, db.y, db.z, db.w};
#pragma unroll
    for (int ky = 0; ky < 3; ky++)
#pragma unroll
        for (int kx = 0; kx < 3; kx++) {
            int yy = i + ky - 1, xx = j + kx - 1;
            if ((unsigned)yy < (unsigned)HH && (unsigned)xx < (unsigned)WW) {
                float4 yv = *reinterpret_cast<const float4*>(
                    &g_y[((b * HH + yy) * WW + xx) * CC + c4]);
                int t = ky * 3 + kx;
                v[0] += yv.x * dws[(c4 + 0) * 9 + t];
                v[1] += yv.y * dws[(c4 + 1) * 9 + t];
                v[2] += yv.z * dws[(c4 + 2) * 9 + t];
                v[3] += yv.w * dws[(c4 + 3) * 9 + t];
            }
        }
    float s = v[0] + v[1] + v[2] + v[3];
#pragma unroll
    for (int o = 16; o; o >>= 1) s += __shfl_xor_sync(0xffffffffu, s, o);
    float mu = s * (1.f / 128.f);
    float d2 = 0.f;
#pragma unroll
    for (int q = 0; q < 4; q++) { float t = v[q] - mu; d2 += t * t; }
#pragma unroll
    for (int o = 16; o; o >>= 1) d2 += __shfl_xor_sync(0xffffffffu, d2, o);
    float inv = rsqrtf(d2 * (1.f / 128.f) + 1e-5f);

    float4 lg = *reinterpret_cast<const float4*>(&ln_g[c4]);
    float4 lb = *reinterpret_cast<const float4*>(&ln_b[c4]);
    float gv[4] = {lg.x, lg.y, lg.z, lg.w};
    float bv[4] = {lb.x, lb.y, lb.z, lb.w};
    float4 outv;
    float* op = reinterpret_cast<float*>(&outv);
#pragma unroll
    for (int q = 0; q < 4; q++) {
        float t = (v[q] - mu) * inv * gv[q] + bv[q];
        op[q] = 0.5f * t * (1.f + erff(t * 0.70710678118654752440f));
    }
    *reinterpret_cast<float4*>(&g_d[(size_t)pix * CC + c4]) = outv;
}

// ---------------- DCNv3 core: softmax + bilinear sampling ----------------
__global__ __launch_bounds__(128) void sample_kernel() {
    int pix = blockIdx.x;
    int g = threadIdx.x >> 5, lane = threadIdx.x & 31;
    int b = pix >> 12, rem = pix & 4095;
    int i = rem >> 6, j = rem & 63;
    const float* omr = g_om + (size_t)pix * OMS;

    float lg[9];
    float mx = -1e30f;
#pragma unroll
    for (int p = 0; p < 9; p++) { lg[p] = omr[72 + g * 9 + p]; mx = fmaxf(mx, lg[p]); }
    float sum = 0.f;
#pragma unroll
    for (int p = 0; p < 9; p++) { lg[p] = expf(lg[p] - mx); sum += lg[p]; }
    float minv = 1.f / sum;

    int cbase = g * GC + lane;
    const float* xpb = g_xp + (size_t)b * (HP * WP * CC);
    float acc = 0.f;
#pragma unroll
    for (int p = 0; p < 9; p++) {
        float offx = omr[(g * 9 + p) * 2 + 0];
        float offy = omr[(g * 9 + p) * 2 + 1];
        float ix = (float)(j + p / 3) + offx;
        float iy = (float)(i + (p - (p / 3) * 3)) + offy;
        float x0f = floorf(ix), y0f = floorf(iy);
        float wx1 = ix - x0f, wy1 = iy - y0f;
        float wx0 = 1.f - wx1, wy0 = 1.f - wy1;
        int x0 = (int)x0f, y0 = (int)y0f;
        float v00 = 0.f, v10 = 0.f, v01 = 0.f, v11 = 0.f;
        bool xv0 = (x0 >= 0) & (x0 < WP);
        bool xv1 = (x0 + 1 >= 0) & (x0 + 1 < WP);
        bool yv0 = (y0 >= 0) & (y0 < HP);
        bool yv1 = (y0 + 1 >= 0) & (y0 + 1 < HP);
        if (yv0) {
            if (xv0) v00 = xpb[(y0 * WP + x0) * CC + cbase];
            if (xv1) v10 = xpb[(y0 * WP + x0 + 1) * CC + cbase];
        }
        if (yv1) {
            if (xv0) v01 = xpb[((y0 + 1) * WP + x0) * CC + cbase];
            if (xv1) v11 = xpb[((y0 + 1) * WP + x0 + 1) * CC + cbase];
        }
        float bi = (v00 * wx0 + v10 * wx1) * wy0 + (v01 * wx0 + v11 * wx1) * wy1;
        acc += (lg[p] * minv) * bi;
    }
    g_sam[(size_t)pix * CC + cbase] = acc;
}

// ---------------- launch ----------------
extern "C" void kernel_launch(void* const* d_in, const int* in_sizes, int n_in,
                              void* d_out, int out_size) {
    const float* x          = (const float*)d_in[0];
    const float* conv_w     = (const float*)d_in[1];
    const float* conv_b     = (const float*)d_in[2];
    const float* in_proj_w  = (const float*)d_in[3];
    const float* in_proj_b  = (const float*)d_in[4];
    const float* dw_w       = (const float*)d_in[5];
    const float* dw_b       = (const float*)d_in[6];
    const float* ln_g       = (const float*)d_in[7];
    const float* ln_b       = (const float*)d_in[8];
    const float* off_w      = (const float*)d_in[9];
    const float* off_b      = (const float*)d_in[10];
    const float* mask_w     = (const float*)d_in[11];
    const float* mask_b     = (const float*)d_in[12];
    const float* out_proj_w = (const float*)d_in[13];
    const float* out_proj_b = (const float*)d_in[14];
    float* out = (float*)d_out;

    float *p_xpad, *p_y, *p_xp, *p_d, *p_om, *p_sam, *p_bt, *p_bcat;
    cudaGetSymbolAddress((void**)&p_xpad, g_xpad);
    cudaGetSymbolAddress((void**)&p_y,    g_y);
    cudaGetSymbolAddress((void**)&p_xp,   g_xp);
    cudaGetSymbolAddress((void**)&p_d,    g_d);
    cudaGetSymbolAddress((void**)&p_om,   g_om);
    cudaGetSymbolAddress((void**)&p_sam,  g_sam);
    cudaGetSymbolAddress((void**)&p_bt,   g_bt);
    cudaGetSymbolAddress((void**)&p_bcat, g_bcat);

    const int SMEM_GEMM = 2 * 128 * LDA * 4;  // 135168
    static int attr_done = 0;
    cudaFuncSetAttribute(mma_gemm_kernel,
                         cudaFuncAttributeMaxDynamicSharedMemorySize, SMEM_GEMM);
    (void)attr_done;

    // 1. zero pad ring of g_xp (interior fully rewritten by GEMM2 each replay)
    ring_zero_kernel<<<(BB * 260 * 32 + 255) / 256, 256>>>();
    // 2. weight prep (tf32 [k][n] B tiles)
    prep_weights_kernel<<<(4 * 16384 + 128 + 255) / 256, 256>>>(
        conv_w, in_proj_w, off_w, mask_w, off_b, mask_b, out_proj_w);
    // 3. NCHW -> NHWC transpose + pad
    {
        dim3 grid(BB * HH, WW / 32, CC / 32);
        transpose_pad_kernel<<<grid, dim3(32, 32)>>>(x);
    }
    // 4. GEMM1: y = xpad @ conv_w^T + conv_b
    mma_gemm_kernel<<<NPIX / 128, 256, SMEM_GEMM>>>(p_xpad, p_bt + 0 * 16384, conv_b, p_y, 0);
    // 5. GEMM2: x_proj = y @ in_proj_w + b -> padded g_xp
    mma_gemm_kernel<<<NPIX / 128, 256, SMEM_GEMM>>>(p_y, p_bt + 1 * 16384, in_proj_b, p_xp, 1);
    // 6. depthwise + LN + GELU
    dw_ln_gelu_kernel<<<NPIX / 8, 256>>>(dw_w, dw_b, ln_g, ln_b);
    // 7. GEMM3: [offset|logits|pad] = d @ wcat + bcat
    mma_gemm_kernel<<<NPIX / 128, 256, SMEM_GEMM>>>(p_d, p_bt + 2 * 16384, p_bcat, p_om, 0);
    // 8. softmax + bilinear sampling
    sample_kernel<<<NPIX, 128>>>();
    // 9. GEMM4: out = sampled @ out_proj_w + b, NCHW scatter
    mma_gemm_kernel<<<NPIX / 128, 256, SMEM_GEMM>>>(p_sam, p_bt + 3 * 16384, out_proj_b, out, 2);
}

// round 5
// speedup vs baseline: 1.8024x; 1.1417x over previous
#include <cuda_runtime.h>
#include <math.h>
#include <stdint.h>

// ---------------- problem constants ----------------
#define BB   8
#define CC   128
#define H0   62
#define W0   62
#define HH   64
#define WW   64
#define HP   66
#define WP   66
#define GG   4
#define PP   9
#define GC   32
#define NPIX (BB*HH*WW)        // 32768
#define OMS  128               // padded om row stride

// ---------------- scratch (device globals) ----------------
__device__ float g_xpad[BB*HH*WW*CC];   // x in NHWC, zero ring
__device__ float g_y   [BB*HH*WW*CC];   // conv1x1 output NHWC
__device__ float g_xp  [BB*HP*WP*CC];   // x_proj padded NHWC
__device__ float g_d   [BB*HH*WW*CC];   // dw+LN+GELU NHWC
__device__ float g_om  [NPIX*OMS];      // offsets(72)+logits(36)+pad
__device__ float g_sam [NPIX*CC];       // sampled NHWC
__device__ float g_bt  [4*128*128];     // 4 pre-transposed tf32 B tiles, [k][n]
__device__ float g_bcat[128];           // padded off/mask bias

// ---------------- helpers ----------------
__device__ __forceinline__ float f2tf(float x) {
    uint32_t u;
    asm("cvt.rn.tf32.f32 %0, %1;" : "=r"(u) : "f"(x));
    return __uint_as_float(u);
}
__device__ __forceinline__ void mma_tf32(float c[4], const uint32_t a[4],
                                         uint32_t b0, uint32_t b1) {
    asm volatile(
        "mma.sync.aligned.m16n8k8.row.col.f32.tf32.tf32.f32 "
        "{%0,%1,%2,%3}, {%4,%5,%6,%7}, {%8,%9}, {%0,%1,%2,%3};"
        : "+f"(c[0]), "+f"(c[1]), "+f"(c[2]), "+f"(c[3])
        : "r"(a[0]), "r"(a[1]), "r"(a[2]), "r"(a[3]), "r"(b0), "r"(b1));
}

// ---------------- weight prep ----------------
__global__ void prep_weights_kernel(const float* __restrict__ conv_w,
                                    const float* __restrict__ in_proj_w,
                                    const float* __restrict__ off_w,
                                    const float* __restrict__ mask_w,
                                    const float* __restrict__ off_b,
                                    const float* __restrict__ mask_b,
                                    const float* __restrict__ out_proj_w) {
    int idx = blockIdx.x * blockDim.x + threadIdx.x;
    const int TB = 4 * 128 * 128;
    if (idx < TB) {
        int w = idx >> 14;
        int rem = idx & 16383;
        int k = rem >> 7, n = rem & 127;
        float v;
        if (w == 0)      v = conv_w[n * 128 + k];
        else if (w == 1) v = in_proj_w[k * 128 + n];
        else if (w == 2) v = (n < 72) ? off_w[k * 72 + n]
                           : (n < 108) ? mask_w[k * 36 + (n - 72)] : 0.f;
        else             v = out_proj_w[k * 128 + n];
        g_bt[idx] = f2tf(v);
    } else if (idx < TB + 128) {
        int n = idx - TB;
        g_bcat[n] = (n < 72) ? off_b[n] : (n < 108) ? mask_b[n - 72] : 0.f;
    }
}

// ---------------- zero only the pad ring of g_xp ----------------
__global__ void ring_zero_kernel() {
    int idx = blockIdx.x * blockDim.x + threadIdx.x;
    if (idx >= BB * 260 * 32) return;
    int c4 = (idx & 31) * 4;
    int t = idx >> 5;
    int b = t / 260, p = t % 260;
    int r, cl;
    if (p < 66)       { r = 0;        cl = p; }
    else if (p < 132) { r = 65;       cl = p - 66; }
    else if (p < 196) { r = p - 131;  cl = 0; }
    else              { r = p - 195;  cl = 65; }
    *reinterpret_cast<float4*>(&g_xp[(((size_t)b * HP + r) * WP + cl) * CC + c4]) =
        make_float4(0.f, 0.f, 0.f, 0.f);
}

// ---------------- NCHW -> NHWC transpose with zero pad ring ----------------
__global__ void transpose_pad_kernel(const float* __restrict__ x) {
    __shared__ float s[32][33];
    int bi = blockIdx.x;
    int b = bi >> 6, i = bi & 63;
    int j0 = blockIdx.y * 32, c0 = blockIdx.z * 32;
    int tx = threadIdx.x, ty = threadIdx.y;
    int j = j0 + tx;
    float v = 0.f;
    if (i >= 1 && i <= 62 && j >= 1 && j <= 62)
        v = x[((b * CC + c0 + ty) * H0 + (i - 1)) * W0 + (j - 1)];
    s[ty][tx] = v;
    __syncthreads();
    int jw = j0 + ty;
    g_xpad[((b * HH + i) * WW + jw) * CC + c0 + tx] = s[tx][ty];
}

// ================= shared GEMM machinery =================
// CTA tile: 256(M) x 128(N) x 128(K); 512 threads = 16 warps (4m x 4n); warp 64x32.
#define LDA 132
#define SM_A_ELEMS (256 * LDA)
#define SM_B_ELEMS (128 * LDA)
#define SMEM_GEMM ((SM_A_ELEMS + SM_B_ELEMS) * 4)

struct Frag { float acc[4][4][4]; };

__device__ __forceinline__ void mma_stage(float* sA, float* sB, Frag& F,
                                          int wm, int wn, int g, int tig) {
#pragma unroll
    for (int mt = 0; mt < 4; mt++)
#pragma unroll
        for (int nt = 0; nt < 4; nt++)
#pragma unroll
            for (int q = 0; q < 4; q++) F.acc[mt][nt][q] = 0.f;
#pragma unroll
    for (int ks = 0; ks < 16; ks++) {
        int k0 = ks * 8;
        uint32_t af[4][4];
#pragma unroll
        for (int mt = 0; mt < 4; mt++) {
            int rb = wm * 64 + mt * 16 + g;
            af[mt][0] = __float_as_uint(sA[rb * LDA + k0 + tig]);
            af[mt][1] = __float_as_uint(sA[(rb + 8) * LDA + k0 + tig]);
            af[mt][2] = __float_as_uint(sA[rb * LDA + k0 + tig + 4]);
            af[mt][3] = __float_as_uint(sA[(rb + 8) * LDA + k0 + tig + 4]);
        }
#pragma unroll
        for (int nt = 0; nt < 4; nt++) {
            int cb = wn * 32 + nt * 8 + g;
            uint32_t b0 = __float_as_uint(sB[(k0 + tig) * LDA + cb]);
            uint32_t b1 = __float_as_uint(sB[(k0 + tig + 4) * LDA + cb]);
#pragma unroll
            for (int mt = 0; mt < 4; mt++) mma_tf32(F.acc[mt][nt], af[mt], b0, b1);
        }
    }
}

// load 128x128 B tile (pre-tf32, [k][n]) into sB: 4096 float4 / 512 thr = 8 each
__device__ __forceinline__ void load_B(const float* __restrict__ Bt, float* sB, int tid) {
#pragma unroll
    for (int it = 0; it < 8; it++) {
        int idx = it * 512 + tid;
        int r = idx >> 5, c4 = (idx & 31) * 4;
        *reinterpret_cast<float4*>(&sB[r * LDA + c4]) =
            *reinterpret_cast<const float4*>(&Bt[(size_t)r * 128 + c4]);
    }
}
// load 256x128 A tile with tf32 convert: 8192 float4 / 512 thr = 16 each
__device__ __forceinline__ void load_A(const float* __restrict__ A, float* sA,
                                       int m0, int tid) {
#pragma unroll
    for (int it = 0; it < 16; it++) {
        int idx = it * 512 + tid;
        int r = idx >> 5, c4 = (idx & 31) * 4;
        float4 v = *reinterpret_cast<const float4*>(&A[(size_t)(m0 + r) * 128 + c4]);
        v.x = f2tf(v.x); v.y = f2tf(v.y); v.z = f2tf(v.z); v.w = f2tf(v.w);
        *reinterpret_cast<float4*>(&sA[r * LDA + c4]) = v;
    }
}

// ---------------- fused GEMM1+GEMM2: y = X@W1+b1 (-> g_y), xp = y@W2+b2 (-> g_xp padded) ----
__global__ __launch_bounds__(512) void dual_gemm_kernel(
    const float* __restrict__ Bt1, const float* __restrict__ bias1,
    const float* __restrict__ Bt2, const float* __restrict__ bias2) {
    extern __shared__ float sm[];
    float* sA = sm;
    float* sB = sm + SM_A_ELEMS;
    int tid = threadIdx.x;
    int w = tid >> 5, lane = tid & 31;
    int g = lane >> 2, tig = lane & 3;
    int wm = w >> 2, wn = w & 3;
    int m0 = blockIdx.x * 256;

    load_A(g_xpad, sA, m0, tid);
    load_B(Bt1, sB, tid);
    __syncthreads();

    Frag F;
    mma_stage(sA, sB, F, wm, wn, g, tig);
    __syncthreads();   // done reading sA/sB; safe to overwrite

    // epilogue 1: +bias1 -> g_y  AND tf32 copy into sA for stage 2
#pragma unroll
    for (int mt = 0; mt < 4; mt++) {
        int ml_a = wm * 64 + mt * 16 + g;
        int ml_b = ml_a + 8;
#pragma unroll
        for (int nt = 0; nt < 4; nt++) {
            int cb = wn * 32 + nt * 8 + 2 * tig;
            float bx = __ldg(&bias1[cb]), by = __ldg(&bias1[cb + 1]);
            float ax = F.acc[mt][nt][0] + bx, ay = F.acc[mt][nt][1] + by;
            float bx2 = F.acc[mt][nt][2] + bx, by2 = F.acc[mt][nt][3] + by;
            *reinterpret_cast<float2*>(&g_y[(size_t)(m0 + ml_a) * 128 + cb]) =
                make_float2(ax, ay);
            *reinterpret_cast<float2*>(&g_y[(size_t)(m0 + ml_b) * 128 + cb]) =
                make_float2(bx2, by2);
            sA[ml_a * LDA + cb] = f2tf(ax);
            sA[ml_a * LDA + cb + 1] = f2tf(ay);
            sA[ml_b * LDA + cb] = f2tf(bx2);
            sA[ml_b * LDA + cb + 1] = f2tf(by2);
        }
    }
    load_B(Bt2, sB, tid);
    __syncthreads();

    mma_stage(sA, sB, F, wm, wn, g, tig);

    // epilogue 2: +bias2 -> g_xp at (r+1, c+1)
#pragma unroll
    for (int mt = 0; mt < 4; mt++) {
        int m_a = m0 + wm * 64 + mt * 16 + g;
        int m_b = m_a + 8;
        int ba = m_a >> 12, ra = m_a & 4095;
        int bb = m_b >> 12, rb = m_b & 4095;
        int r1 = ra >> 6, c1 = ra & 63;
        int r2 = rb >> 6, c2 = rb & 63;
        float* da = &g_xp[(((size_t)ba * HP + r1 + 1) * WP + c1 + 1) * CC];
        float* db = &g_xp[(((size_t)bb * HP + r2 + 1) * WP + c2 + 1) * CC];
#pragma unroll
        for (int nt = 0; nt < 4; nt++) {
            int cb = wn * 32 + nt * 8 + 2 * tig;
            float bx = __ldg(&bias2[cb]), by = __ldg(&bias2[cb + 1]);
            *reinterpret_cast<float2*>(da + cb) =
                make_float2(F.acc[mt][nt][0] + bx, F.acc[mt][nt][1] + by);
            *reinterpret_cast<float2*>(db + cb) =
                make_float2(F.acc[mt][nt][2] + bx, F.acc[mt][nt][3] + by);
        }
    }
}

// ---------------- single GEMM (modes: 0 row-major, 2 NCHW scatter) ----------------
__global__ __launch_bounds__(512) void mma_gemm_kernel(
    const float* __restrict__ A, const float* __restrict__ Bt,
    const float* __restrict__ bias, float* __restrict__ C, int mode) {
    extern __shared__ float sm[];
    float* sA = sm;
    float* sB = sm + SM_A_ELEMS;
    int tid = threadIdx.x;
    int w = tid >> 5, lane = tid & 31;
    int g = lane >> 2, tig = lane & 3;
    int wm = w >> 2, wn = w & 3;
    int m0 = blockIdx.x * 256;

    load_A(A, sA, m0, tid);
    load_B(Bt, sB, tid);
    __syncthreads();

    Frag F;
    mma_stage(sA, sB, F, wm, wn, g, tig);

#pragma unroll
    for (int mt = 0; mt < 4; mt++) {
        int m_a = m0 + wm * 64 + mt * 16 + g;
        int m_b = m_a + 8;
        int ba = m_a >> 12, ra = m_a & 4095;
        int bb = m_b >> 12, rb = m_b & 4095;
#pragma unroll
        for (int nt = 0; nt < 4; nt++) {
            int cb = wn * 32 + nt * 8 + 2 * tig;
            float bx = __ldg(&bias[cb]), by = __ldg(&bias[cb + 1]);
            float2 oa = make_float2(F.acc[mt][nt][0] + bx, F.acc[mt][nt][1] + by);
            float2 ob = make_float2(F.acc[mt][nt][2] + bx, F.acc[mt][nt][3] + by);
            if (mode == 0) {
                *reinterpret_cast<float2*>(&C[(size_t)m_a * 128 + cb]) = oa;
                *reinterpret_cast<float2*>(&C[(size_t)m_b * 128 + cb]) = ob;
            } else {
                C[((size_t)ba * CC + cb    ) * 4096 + ra] = oa.x;
                C[((size_t)ba * CC + cb + 1) * 4096 + ra] = oa.y;
                C[((size_t)bb * CC + cb    ) * 4096 + rb] = ob.x;
                C[((size_t)bb * CC + cb + 1) * 4096 + rb] = ob.y;
            }
        }
    }
}

// ---------------- fused depthwise 3x3 + LayerNorm + GELU ----------------
__global__ __launch_bounds__(256) void dw_ln_gelu_kernel(
    const float* __restrict__ dw_w, const float* __restrict__ dw_b,
    const float* __restrict__ ln_g, const float* __restrict__ ln_b) {
    __shared__ float dws[CC * 9];
    int tid = threadIdx.x;
    for (int t = tid; t < CC * 9; t += 256) dws[t] = dw_w[t];
    __syncthreads();

    int warp = tid >> 5, lane = tid & 31;
    int pix = blockIdx.x * 8 + warp;
    int b = pix >> 12, rem = pix & 4095;
    int i = rem >> 6, j = rem & 63;
    int c4 = lane * 4;

    float4 db = *reinterpret_cast<const float4*>(&dw_b[c4]);
    float v[4] = {db.x, db.y, db.z, db.w};
#pragma unroll
    for (int ky = 0; ky < 3; ky++)
#pragma unroll
        for (int kx = 0; kx < 3; kx++) {
            int yy = i + ky - 1, xx = j + kx - 1;
            if ((unsigned)yy < (unsigned)HH && (unsigned)xx < (unsigned)WW) {
                float4 yv = *reinterpret_cast<const float4*>(
                    &g_y[((b * HH + yy) * WW + xx) * CC + c4]);
                int t = ky * 3 + kx;
                v[0] += yv.x * dws[(c4 + 0) * 9 + t];
                v[1] += yv.y * dws[(c4 + 1) * 9 + t];
                v[2] += yv.z * dws[(c4 + 2) * 9 + t];
                v[3] += yv.w * dws[(c4 + 3) * 9 + t];
            }
        }
    float s = v[0] + v[1] + v[2] + v[3];
#pragma unroll
    for (int o = 16; o; o >>= 1) s += __shfl_xor_sync(0xffffffffu, s, o);
    float mu = s * (1.f / 128.f);
    float d2 = 0.f;
#pragma unroll
    for (int q = 0; q < 4; q++) { float t = v[q] - mu; d2 += t * t; }
#pragma unroll
    for (int o = 16; o; o >>= 1) d2 += __shfl_xor_sync(0xffffffffu, d2, o);
    float inv = rsqrtf(d2 * (1.f / 128.f) + 1e-5f);

    float4 lg = *reinterpret_cast<const float4*>(&ln_g[c4]);
    float4 lb = *reinterpret_cast<const float4*>(&ln_b[c4]);
    float gv[4] = {lg.x, lg.y, lg.z, lg.w};
    float bv[4] = {lb.x, lb.y, lb.z, lb.w};
    float4 outv;
    float* op = reinterpret_cast<float*>(&outv);
#pragma unroll
    for (int q = 0; q < 4; q++) {
        float t = (v[q] - mu) * inv * gv[q] + bv[q];
        op[q] = 0.5f * t * (1.f + erff(t * 0.70710678118654752440f));
    }
    *reinterpret_cast<float4*>(&g_d[(size_t)pix * CC + c4]) = outv;
}

// ---------------- DCNv3 core: softmax + bilinear sampling ----------------
// block = 2x2 pixel tile x 4 groups = 16 warps (512 thr); L1 reuse across the tile
__global__ __launch_bounds__(512) void sample_kernel() {
    int w = threadIdx.x >> 5, lane = threadIdx.x & 31;
    int pl = w >> 2;                 // pixel in 2x2 tile
    int g = w & 3;
    int blk = blockIdx.x;            // b*1024 + ty*32 + tx
    int tx = blk & 31, ty = (blk >> 5) & 31, b = blk >> 10;
    int i = ty * 2 + (pl >> 1);
    int j = tx * 2 + (pl & 1);
    int pix = (b << 12) + (i << 6) + j;
    const float* omr = g_om + (size_t)pix * OMS;

    float lg[9];
    float mx = -1e30f;
#pragma unroll
    for (int p = 0; p < 9; p++) { lg[p] = omr[72 + g * 9 + p]; mx = fmaxf(mx, lg[p]); }
    float sum = 0.f;
#pragma unroll
    for (int p = 0; p < 9; p++) { lg[p] = expf(lg[p] - mx); sum += lg[p]; }
    float minv = 1.f / sum;

    int cbase = g * GC + lane;
    const float* xpb = g_xp + (size_t)b * (HP * WP * CC);
    float acc = 0.f;
#pragma unroll
    for (int p = 0; p < 9; p++) {
        float offx = omr[(g * 9 + p) * 2 + 0];
        float offy = omr[(g * 9 + p) * 2 + 1];
        float ix = (float)(j + p / 3) + offx;
        float iy = (float)(i + (p - (p / 3) * 3)) + offy;
        float x0f = floorf(ix), y0f = floorf(iy);
        float wx1 = ix - x0f, wy1 = iy - y0f;
        float wx0 = 1.f - wx1, wy0 = 1.f - wy1;
        int x0 = (int)x0f, y0 = (int)y0f;
        float v00 = 0.f, v10 = 0.f, v01 = 0.f, v11 = 0.f;
        bool xv0 = (x0 >= 0) & (x0 < WP);
        bool xv1 = (x0 + 1 >= 0) & (x0 + 1 < WP);
        bool yv0 = (y0 >= 0) & (y0 < HP);
        bool yv1 = (y0 + 1 >= 0) & (y0 + 1 < HP);
        if (yv0) {
            if (xv0) v00 = xpb[(y0 * WP + x0) * CC + cbase];
            if (xv1) v10 = xpb[(y0 * WP + x0 + 1) * CC + cbase];
        }
        if (yv1) {
            if (xv0) v01 = xpb[((y0 + 1) * WP + x0) * CC + cbase];
            if (xv1) v11 = xpb[((y0 + 1) * WP + x0 + 1) * CC + cbase];
        }
        float bi = (v00 * wx0 + v10 * wx1) * wy0 + (v01 * wx0 + v11 * wx1) * wy1;
        acc += (lg[p] * minv) * bi;
    }
    g_sam[(size_t)pix * CC + cbase] = acc;
}

// ---------------- launch ----------------
extern "C" void kernel_launch(void* const* d_in, const int* in_sizes, int n_in,
                              void* d_out, int out_size) {
    const float* x          = (const float*)d_in[0];
    const float* conv_w     = (const float*)d_in[1];
    const float* conv_b     = (const float*)d_in[2];
    const float* in_proj_w  = (const float*)d_in[3];
    const float* in_proj_b  = (const float*)d_in[4];
    const float* dw_w       = (const float*)d_in[5];
    const float* dw_b       = (const float*)d_in[6];
    const float* ln_g       = (const float*)d_in[7];
    const float* ln_b       = (const float*)d_in[8];
    const float* off_w      = (const float*)d_in[9];
    const float* off_b      = (const float*)d_in[10];
    const float* mask_w     = (const float*)d_in[11];
    const float* mask_b     = (const float*)d_in[12];
    const float* out_proj_w = (const float*)d_in[13];
    const float* out_proj_b = (const float*)d_in[14];
    float* out = (float*)d_out;

    float *p_d, *p_om, *p_sam, *p_bt, *p_bcat;
    cudaGetSymbolAddress((void**)&p_d,    g_d);
    cudaGetSymbolAddress((void**)&p_om,   g_om);
    cudaGetSymbolAddress((void**)&p_sam,  g_sam);
    cudaGetSymbolAddress((void**)&p_bt,   g_bt);
    cudaGetSymbolAddress((void**)&p_bcat, g_bcat);

    cudaFuncSetAttribute(dual_gemm_kernel,
                         cudaFuncAttributeMaxDynamicSharedMemorySize, SMEM_GEMM);
    cudaFuncSetAttribute(mma_gemm_kernel,
                         cudaFuncAttributeMaxDynamicSharedMemorySize, SMEM_GEMM);

    // 1. zero pad ring of g_xp
    ring_zero_kernel<<<(BB * 260 * 32 + 255) / 256, 256>>>();
    // 2. weight prep
    prep_weights_kernel<<<(4 * 16384 + 128 + 255) / 256, 256>>>(
        conv_w, in_proj_w, off_w, mask_w, off_b, mask_b, out_proj_w);
    // 3. NCHW -> NHWC transpose + pad
    {
        dim3 grid(BB * HH, WW / 32, CC / 32);
        transpose_pad_kernel<<<grid, dim3(32, 32)>>>(x);
    }
    // 4. fused GEMM1+GEMM2
    dual_gemm_kernel<<<NPIX / 256, 512, SMEM_GEMM>>>(
        p_bt + 0 * 16384, conv_b, p_bt + 1 * 16384, in_proj_b);
    // 5. depthwise + LN + GELU
    dw_ln_gelu_kernel<<<NPIX / 8, 256>>>(dw_w, dw_b, ln_g, ln_b);
    // 6. GEMM3: [offset|logits|pad] = d @ wcat + bcat
    mma_gemm_kernel<<<NPIX / 256, 512, SMEM_GEMM>>>(p_d, p_bt + 2 * 16384, p_bcat, p_om, 0);
    // 7. softmax + bilinear sampling (2x2 pixel tiles)
    sample_kernel<<<BB * 32 * 32, 512>>>();
    // 8. GEMM4: out = sampled @ out_proj_w + b, NCHW scatter
    mma_gemm_kernel<<<NPIX / 256, 512, SMEM_GEMM>>>(p_sam, p_bt + 3 * 16384, out_proj_b, out, 2);
}